// round 1
// baseline (speedup 1.0000x reference)
#include <cuda_runtime.h>

// Problem constants
#define H_ 3
#define L_ 2
#define B_ 16
#define S_ 512
#define D_ 512
#define F_ (H_ * L_ * D_)   // 3072

// Scratch (no cudaMalloc allowed)
__device__ float g_Ax[(size_t)B_ * S_ * D_];        // 16 MB
__device__ float g_final[(size_t)B_ * S_ * F_];     // 96 MB
__device__ float g_denom[(size_t)H_ * B_ * S_];     // 96 KB

// ---------------------------------------------------------------------------
// denom[i,b,s] = 1 + sum_t adj[i,b,s,t]   (one warp per row)
// ---------------------------------------------------------------------------
__global__ void denom_kernel(const float* __restrict__ adj, float* __restrict__ den)
{
    int gw   = (blockIdx.x * blockDim.x + threadIdx.x) >> 5;
    int lane = threadIdx.x & 31;
    if (gw >= H_ * B_ * S_) return;
    const float* p = adj + (long)gw * S_;
    float s = 0.f;
    #pragma unroll 4
    for (int t = lane; t < S_; t += 32) s += p[t];
    #pragma unroll
    for (int o = 16; o > 0; o >>= 1) s += __shfl_xor_sync(0xffffffffu, s, o);
    if (lane == 0) den[gw] = s + 1.0f;
}

// ---------------------------------------------------------------------------
// Generic 128x128x8 fp32 GEMM, 256 threads, 8x8 per-thread tile.
//   BT=false: C = A[M,K] * B[K,N]        (both row-major)
//   BT=true : C = A[M,K] * B[N,K]^T      (B row-major [N,K])
// MODE 0: C = acc + epi[m][n]                                (Ax + X)
// MODE 1: C = relu((acc + biasScale*bias[n]) / denom[z*M+m]) (GCN layer)
// MODE 2: C = acc + bias[n] + epi[m][n]                      (final + residual)
// All of M,N divisible by 128; K divisible by 8. No bounds checks.
// ---------------------------------------------------------------------------
template <bool BT, int MODE>
__global__ __launch_bounds__(256, 2)
void sgemm(const float* __restrict__ A, const float* __restrict__ Bm,
           float* __restrict__ C,
           int M, int N, int K,
           int lda, int ldb, int ldc,
           long aBatch, long bBatch, long cBatch,
           const float* __restrict__ epi, int epiLd, long epiBatch,
           const float* __restrict__ bias, float biasScale,
           const float* __restrict__ denom)
{
    __shared__ float As[8][132];
    __shared__ float Bs[8][132];

    const int tid = threadIdx.x;
    const int bx = blockIdx.x, by = blockIdx.y, z = blockIdx.z;
    const int tx = tid & 15, ty = tid >> 4;

    const float* Ab = A + (long)z * aBatch + (long)(by * 128) * lda;
    const float* Bb;
    if (BT) Bb = Bm + (long)z * bBatch + (long)(bx * 128) * ldb;
    else    Bb = Bm + (long)z * bBatch + bx * 128;

    const int arow  = tid >> 1;          // 0..127
    const int akoff = (tid & 1) * 4;     // 0 or 4
    const int bkrow = tid >> 5;          // 0..7   (NN only)
    const int bcol  = (tid & 31) * 4;    // 0..124 (NN only)

    float acc[8][8];
    #pragma unroll
    for (int i = 0; i < 8; ++i)
        #pragma unroll
        for (int j = 0; j < 8; ++j) acc[i][j] = 0.f;

    const int numK = K >> 3;

    // prefetch tile 0
    float4 aReg = *(const float4*)(Ab + (long)arow * lda + akoff);
    float4 bReg;
    if (BT) bReg = *(const float4*)(Bb + (long)arow * ldb + akoff);
    else    bReg = *(const float4*)(Bb + (long)bkrow * ldb + bcol);

    As[akoff + 0][arow] = aReg.x;
    As[akoff + 1][arow] = aReg.y;
    As[akoff + 2][arow] = aReg.z;
    As[akoff + 3][arow] = aReg.w;
    if (BT) {
        Bs[akoff + 0][arow] = bReg.x;
        Bs[akoff + 1][arow] = bReg.y;
        Bs[akoff + 2][arow] = bReg.z;
        Bs[akoff + 3][arow] = bReg.w;
    } else {
        *(float4*)&Bs[bkrow][bcol] = bReg;
    }
    __syncthreads();

    for (int kt = 0; kt < numK; ++kt) {
        float4 aN, bN;
        const bool has = (kt + 1) < numK;
        if (has) {
            const int k0 = (kt + 1) * 8;
            aN = *(const float4*)(Ab + (long)arow * lda + k0 + akoff);
            if (BT) bN = *(const float4*)(Bb + (long)arow * ldb + k0 + akoff);
            else    bN = *(const float4*)(Bb + (long)(k0 + bkrow) * ldb + bcol);
        }

        #pragma unroll
        for (int k = 0; k < 8; ++k) {
            float4 a0 = *(const float4*)&As[k][ty * 4];
            float4 a1 = *(const float4*)&As[k][ty * 4 + 64];
            float4 b0 = *(const float4*)&Bs[k][tx * 4];
            float4 b1 = *(const float4*)&Bs[k][tx * 4 + 64];
            float av[8] = {a0.x, a0.y, a0.z, a0.w, a1.x, a1.y, a1.z, a1.w};
            float bv[8] = {b0.x, b0.y, b0.z, b0.w, b1.x, b1.y, b1.z, b1.w};
            #pragma unroll
            for (int i = 0; i < 8; ++i)
                #pragma unroll
                for (int j = 0; j < 8; ++j)
                    acc[i][j] = fmaf(av[i], bv[j], acc[i][j]);
        }
        __syncthreads();
        if (has) {
            As[akoff + 0][arow] = aN.x;
            As[akoff + 1][arow] = aN.y;
            As[akoff + 2][arow] = aN.z;
            As[akoff + 3][arow] = aN.w;
            if (BT) {
                Bs[akoff + 0][arow] = bN.x;
                Bs[akoff + 1][arow] = bN.y;
                Bs[akoff + 2][arow] = bN.z;
                Bs[akoff + 3][arow] = bN.w;
            } else {
                *(float4*)&Bs[bkrow][bcol] = bN;
            }
        }
        __syncthreads();
    }

    // -------- epilogue --------
    float* Cb = C + (long)z * cBatch;
    const float* Eb = epi ? (epi + (long)z * epiBatch) : nullptr;
    const int row0 = by * 128 + ty * 4;
    const int col0 = bx * 128 + tx * 4;

    #pragma unroll
    for (int ih = 0; ih < 2; ++ih) {
        #pragma unroll
        for (int i = 0; i < 4; ++i) {
            const int m = row0 + ih * 64 + i;
            float invd = 1.f;
            if (MODE == 1) invd = 1.0f / denom[(long)z * M + m];
            #pragma unroll
            for (int jh = 0; jh < 2; ++jh) {
                const int n = col0 + jh * 64;
                float4 v;
                v.x = acc[ih * 4 + i][jh * 4 + 0];
                v.y = acc[ih * 4 + i][jh * 4 + 1];
                v.z = acc[ih * 4 + i][jh * 4 + 2];
                v.w = acc[ih * 4 + i][jh * 4 + 3];
                if (MODE == 0) {
                    float4 e = *(const float4*)(Eb + (long)m * epiLd + n);
                    v.x += e.x; v.y += e.y; v.z += e.z; v.w += e.w;
                }
                if (MODE == 1) {
                    v.x = (v.x + biasScale * bias[n + 0]) * invd;
                    v.y = (v.y + biasScale * bias[n + 1]) * invd;
                    v.z = (v.z + biasScale * bias[n + 2]) * invd;
                    v.w = (v.w + biasScale * bias[n + 3]) * invd;
                    v.x = fmaxf(v.x, 0.f); v.y = fmaxf(v.y, 0.f);
                    v.z = fmaxf(v.z, 0.f); v.w = fmaxf(v.w, 0.f);
                }
                if (MODE == 2) {
                    float4 e = *(const float4*)(Eb + (long)m * epiLd + n);
                    v.x += e.x + bias[n + 0];
                    v.y += e.y + bias[n + 1];
                    v.z += e.z + bias[n + 2];
                    v.w += e.w + bias[n + 3];
                }
                *(float4*)(Cb + (long)m * ldc + n) = v;
            }
        }
    }
}

// ---------------------------------------------------------------------------
extern "C" void kernel_launch(void* const* d_in, const int* in_sizes, int n_in,
                              void* d_out, int out_size)
{
    const float* adj = (const float*)d_in[0];   // [H,B,S,S]
    const float* x0  = (const float*)d_in[1];   // [B,S,D]
    // d_in[2], d_in[3]: mask / domain_mask (unused by forward)
    const float* Wg  = (const float*)d_in[4];   // [H*L, D, D]
    const float* bg  = (const float*)d_in[5];   // [H*L, D]
    const float* Wo  = (const float*)d_in[6];   // [D, F]
    const float* bo  = (const float*)d_in[7];   // [D]
    float* out = (float*)d_out;                 // [B,S,D]

    float *Ax, *fin, *den;
    cudaGetSymbolAddress((void**)&Ax,  g_Ax);
    cudaGetSymbolAddress((void**)&fin, g_final);
    cudaGetSymbolAddress((void**)&den, g_denom);

    // denom: H*B*S = 24576 rows, one warp each, 8 warps/block
    denom_kernel<<<(H_ * B_ * S_) / 8, 256>>>(adj, den);

    const dim3 blk(256);
    for (int idx = 0; idx < H_ * L_; ++idx) {
        const int i = idx / L_;
        const int l = idx % L_;
        const float* X  = (l == 0) ? x0 : (fin + (long)(idx - 1) * D_);
        const int  xld  = (l == 0) ? D_ : F_;
        const long xbs  = (l == 0) ? (long)S_ * D_ : (long)S_ * F_;

        // GEMM1 (NN): g_Ax = adj_i @ X + X
        sgemm<false, 0><<<dim3(4, 4, B_), blk>>>(
            adj + (long)i * B_ * S_ * S_, X, Ax,
            S_, D_, S_,
            S_, xld, D_,
            (long)S_ * S_, xbs, (long)S_ * D_,
            X, xld, xbs,
            nullptr, 0.f, nullptr);

        // GEMM2 (NT): final[..,idx*D:..] = relu((g_Ax @ W_idx^T + 2b) / denom)
        sgemm<true, 1><<<dim3(4, 4, B_), blk>>>(
            Ax, Wg + (long)idx * D_ * D_, fin + (long)idx * D_,
            S_, D_, D_,
            D_, D_, F_,
            (long)S_ * D_, 0, (long)S_ * F_,
            nullptr, 0, 0,
            bg + (long)idx * D_, 2.0f,
            den + (long)i * B_ * S_);
    }

    // Final (NT): out = final @ W_out^T + b_out + gcn_inputs   (M = B*S = 8192)
    sgemm<true, 2><<<dim3(4, 64, 1), blk>>>(
        fin, Wo, out,
        B_ * S_, D_, F_,
        F_, F_, D_,
        0, 0, 0,
        x0, D_, 0,
        bo, 1.0f,
        nullptr);
}

// round 3
// speedup vs baseline: 1.7333x; 1.7333x over previous
#include <cuda_runtime.h>
#include <cstdint>

#define H_ 3
#define L_ 2
#define B_ 16
#define S_ 512
#define D_ 512
#define F_ (H_ * L_ * D_)   // 3072

// Scratch (no cudaMalloc allowed)
__device__ float g_Ax[(size_t)B_ * S_ * D_];        // 16 MB
__device__ float g_final[(size_t)B_ * S_ * F_];     // 96 MB
__device__ float g_denom[H_ * B_ * S_];             // 96 KB
__device__ float g_XT[(size_t)B_ * D_ * S_];        // 16 MB (current head layer-0 out, transposed)
__device__ float g_X0T[(size_t)B_ * D_ * S_];       // 16 MB (x0 transposed)

// ---------------------------------------------------------------------------
__device__ __forceinline__ uint32_t smem_u32(const void* p) {
    uint32_t a;
    asm("{ .reg .u64 t; cvta.to.shared.u64 t, %1; cvt.u32.u64 %0, t; }" : "=r"(a) : "l"(p));
    return a;
}
__device__ __forceinline__ uint32_t f2tf(float x) {
    uint32_t r;
    asm("cvt.rna.tf32.f32 %0, %1;" : "=r"(r) : "f"(x));
    return r;
}
#define CP_ASYNC16(dst, src) \
    asm volatile("cp.async.cg.shared.global [%0], [%1], 16;" :: "r"(dst), "l"(src))
#define CP_COMMIT() asm volatile("cp.async.commit_group;")
#define CP_WAIT(n)  asm volatile("cp.async.wait_group %0;" :: "n"(n))

#define MMA_TF32(c, a, b) \
    asm volatile("mma.sync.aligned.m16n8k8.row.col.f32.tf32.tf32.f32 " \
        "{%0,%1,%2,%3}, {%4,%5,%6,%7}, {%8,%9}, {%0,%1,%2,%3};" \
        : "+f"((c)[0]), "+f"((c)[1]), "+f"((c)[2]), "+f"((c)[3]) \
        : "r"((a)[0]), "r"((a)[1]), "r"((a)[2]), "r"((a)[3]), \
          "r"((b)[0]), "r"((b)[1]))

// ---------------------------------------------------------------------------
// denom[i,b,s] = 1 + sum_t adj[i,b,s,t]   (one warp per row)
// ---------------------------------------------------------------------------
__global__ void denom_kernel(const float* __restrict__ adj, float* __restrict__ den)
{
    int gw = (blockIdx.x * blockDim.x + threadIdx.x) >> 5;
    int lane = threadIdx.x & 31;
    if (gw >= H_ * B_ * S_) return;
    const float* p = adj + (long)gw * S_;
    float s = 0.f;
    #pragma unroll 4
    for (int t = lane; t < S_; t += 32) s += p[t];
    #pragma unroll
    for (int o = 16; o > 0; o >>= 1) s += __shfl_xor_sync(0xffffffffu, s, o);
    if (lane == 0) den[gw] = s + 1.0f;
}

// ---------------------------------------------------------------------------
// XT[b][d][s] = X[b][s][d]   (src row stride ldx, batch stride xbatch)
// ---------------------------------------------------------------------------
__global__ void transpose_kernel(const float* __restrict__ X, int ldx, long xbatch,
                                 float* __restrict__ XT)
{
    __shared__ float t[32][33];
    int b = blockIdx.z;
    int s0 = blockIdx.x * 32, d0 = blockIdx.y * 32;
    const float* Xb = X + (long)b * xbatch;
    float* Tb = XT + (size_t)b * D_ * S_;
    int tx = threadIdx.x, ty = threadIdx.y;  // 32 x 8
    #pragma unroll
    for (int i = 0; i < 32; i += 8)
        t[ty + i][tx] = Xb[(long)(s0 + ty + i) * ldx + d0 + tx];
    __syncthreads();
    #pragma unroll
    for (int i = 0; i < 32; i += 8)
        Tb[(size_t)(d0 + ty + i) * S_ + s0 + tx] = t[tx][ty + i];
}

// ---------------------------------------------------------------------------
// TF32 mma.sync GEMM:  C[M,N] = A[M,K] (K-major) * B[N,K]^T (K-major)
// CTA tile 128x128, BK=32, 8 warps each 64x32, cp.async 2-stage pipeline.
// MODE 0: C = acc + epi[m][n]                                  (Ax + X)
// MODE 1: C = relu((acc + biasScale*bias[n]) / denom[z,m])     (GCN layer)
// MODE 2: C = acc + bias[n] + epi[m][n]                        (final + residual)
// ---------------------------------------------------------------------------
constexpr int BM = 128, BN = 128, BK = 32;
constexpr int LDSROW = 36;                        // floats; 36 % 32 == 4 -> conflict-free
constexpr int STAGE_FLOATS = 2 * BM * LDSROW;     // A + B per stage = 9216
constexpr int SMEM_SZ = 2 * STAGE_FLOATS * 4;     // 73728 bytes

template <int MODE>
__global__ __launch_bounds__(256, 2)
void mma_gemm(const float* __restrict__ A, const float* __restrict__ Bm,
              float* __restrict__ C,
              int K, int lda, int ldb, int ldc,
              long aBatch, long bBatch, long cBatch,
              const float* __restrict__ epi, int epiLd, long epiBatch,
              const float* __restrict__ bias, float biasScale,
              const float* __restrict__ denom, int denomStride)
{
    extern __shared__ float smemf[];
    const int tid = threadIdx.x;
    const int wid = tid >> 5, lane = tid & 31;
    const int bx = blockIdx.x, by = blockIdx.y, z = blockIdx.z;

    const uint32_t sbase = smem_u32(smemf);

    const float* Ab = A + (long)z * aBatch + (long)(by * BM) * lda;
    const float* Bb = Bm + (long)z * bBatch + (long)(bx * BN) * ldb;

    // cp.async mapping: 2 threads per row, 4 x 16B chunks each
    const int ldrow = tid >> 1;            // 0..127
    const int ldc0  = (tid & 1) * 16;      // float col 0 or 16

    auto load_stage = [&](int s, int kt) {
        const long k0 = (long)kt * BK + ldc0;
        const float* ag = Ab + (long)ldrow * lda + k0;
        const float* bg = Bb + (long)ldrow * ldb + k0;
        uint32_t da = sbase + (uint32_t)(s * STAGE_FLOATS + ldrow * LDSROW + ldc0) * 4u;
        uint32_t db = da + (uint32_t)(BM * LDSROW) * 4u;
        #pragma unroll
        for (int i = 0; i < 4; ++i) {
            CP_ASYNC16(da + i * 16u, ag + i * 4);
            CP_ASYNC16(db + i * 16u, bg + i * 4);
        }
    };

    // warp tiling: 2 (m) x 4 (n)
    const int m0 = (wid & 1) * 64;
    const int n0 = (wid >> 1) * 32;
    const int lq = lane >> 2;   // 0..7
    const int lr = lane & 3;    // 0..3

    float c[4][4][4];
    #pragma unroll
    for (int mi = 0; mi < 4; ++mi)
        #pragma unroll
        for (int ni = 0; ni < 4; ++ni)
            #pragma unroll
            for (int j = 0; j < 4; ++j) c[mi][ni][j] = 0.f;

    const int numK = K >> 5;

    load_stage(0, 0);
    CP_COMMIT();

    for (int kt = 0; kt < numK; ++kt) {
        const int s = kt & 1;
        if (kt + 1 < numK) {
            load_stage(s ^ 1, kt + 1);
            CP_COMMIT();
            CP_WAIT(1);
        } else {
            CP_WAIT(0);
        }
        __syncthreads();

        const float* Asl = smemf + s * STAGE_FLOATS;
        const float* Bsl = Asl + BM * LDSROW;
        #pragma unroll
        for (int ks = 0; ks < 4; ++ks) {
            const int kc = ks * 8 + lr;
            uint32_t a[4][4], b[4][2];
            #pragma unroll
            for (int mi = 0; mi < 4; ++mi) {
                const int r = m0 + mi * 16 + lq;
                a[mi][0] = f2tf(Asl[r * LDSROW + kc]);
                a[mi][1] = f2tf(Asl[(r + 8) * LDSROW + kc]);
                a[mi][2] = f2tf(Asl[r * LDSROW + kc + 4]);
                a[mi][3] = f2tf(Asl[(r + 8) * LDSROW + kc + 4]);
            }
            #pragma unroll
            for (int ni = 0; ni < 4; ++ni) {
                const int n = n0 + ni * 8 + lq;
                b[ni][0] = f2tf(Bsl[n * LDSROW + kc]);
                b[ni][1] = f2tf(Bsl[n * LDSROW + kc + 4]);
            }
            #pragma unroll
            for (int mi = 0; mi < 4; ++mi)
                #pragma unroll
                for (int ni = 0; ni < 4; ++ni)
                    MMA_TF32(c[mi][ni], a[mi], b[ni]);
        }
        __syncthreads();
    }

    // ---------------- epilogue ----------------
    float* Cb = C + (long)z * cBatch;
    const float* Eb = (MODE == 0 || MODE == 2) ? (epi + (long)z * epiBatch) : nullptr;

    #pragma unroll
    for (int mi = 0; mi < 4; ++mi) {
        const int r0 = by * BM + m0 + mi * 16 + lq;
        float invd0 = 1.f, invd1 = 1.f;
        if (MODE == 1) {
            invd0 = 1.0f / denom[(long)z * denomStride + r0];
            invd1 = 1.0f / denom[(long)z * denomStride + r0 + 8];
        }
        #pragma unroll
        for (int ni = 0; ni < 4; ++ni) {
            const int col = bx * BN + n0 + ni * 8 + 2 * lr;
            float v00 = c[mi][ni][0], v01 = c[mi][ni][1];
            float v10 = c[mi][ni][2], v11 = c[mi][ni][3];
            if (MODE == 1) {
                const float b0 = biasScale * bias[col];
                const float b1 = biasScale * bias[col + 1];
                v00 = fmaxf((v00 + b0) * invd0, 0.f);
                v01 = fmaxf((v01 + b1) * invd0, 0.f);
                v10 = fmaxf((v10 + b0) * invd1, 0.f);
                v11 = fmaxf((v11 + b1) * invd1, 0.f);
            } else if (MODE == 0) {
                const float2 e0 = *(const float2*)(Eb + (long)r0 * epiLd + col);
                const float2 e1 = *(const float2*)(Eb + (long)(r0 + 8) * epiLd + col);
                v00 += e0.x; v01 += e0.y; v10 += e1.x; v11 += e1.y;
            } else {  // MODE 2
                const float2 e0 = *(const float2*)(Eb + (long)r0 * epiLd + col);
                const float2 e1 = *(const float2*)(Eb + (long)(r0 + 8) * epiLd + col);
                const float b0 = bias[col], b1 = bias[col + 1];
                v00 += e0.x + b0; v01 += e0.y + b1;
                v10 += e1.x + b0; v11 += e1.y + b1;
            }
            float2 w0 = {v00, v01}, w1 = {v10, v11};
            *(float2*)(Cb + (long)r0 * ldc + col) = w0;
            *(float2*)(Cb + (long)(r0 + 8) * ldc + col) = w1;
        }
    }
}

// ---------------------------------------------------------------------------
extern "C" void kernel_launch(void* const* d_in, const int* in_sizes, int n_in,
                              void* d_out, int out_size)
{
    const float* adj = (const float*)d_in[0];   // [H,B,S,S]
    const float* x0  = (const float*)d_in[1];   // [B,S,D]
    const float* Wg  = (const float*)d_in[4];   // [H*L, D, D]
    const float* bg  = (const float*)d_in[5];   // [H*L, D]
    const float* Wo  = (const float*)d_in[6];   // [D, F]
    const float* bo  = (const float*)d_in[7];   // [D]
    float* out = (float*)d_out;                 // [B,S,D]

    float *Ax, *fin, *den, *XT, *X0T;
    cudaGetSymbolAddress((void**)&Ax,  g_Ax);
    cudaGetSymbolAddress((void**)&fin, g_final);
    cudaGetSymbolAddress((void**)&den, g_denom);
    cudaGetSymbolAddress((void**)&XT,  g_XT);
    cudaGetSymbolAddress((void**)&X0T, g_X0T);

    cudaFuncSetAttribute(mma_gemm<0>, cudaFuncAttributeMaxDynamicSharedMemorySize, SMEM_SZ);
    cudaFuncSetAttribute(mma_gemm<1>, cudaFuncAttributeMaxDynamicSharedMemorySize, SMEM_SZ);
    cudaFuncSetAttribute(mma_gemm<2>, cudaFuncAttributeMaxDynamicSharedMemorySize, SMEM_SZ);

    denom_kernel<<<(H_ * B_ * S_) / 8, 256>>>(adj, den);
    transpose_kernel<<<dim3(16, 16, B_), dim3(32, 8)>>>(x0, D_, (long)S_ * D_, X0T);

    for (int idx = 0; idx < H_ * L_; ++idx) {
        const int i = idx / L_;
        const int l = idx % L_;
        const float* Xrow = (l == 0) ? x0 : (fin + (long)(idx - 1) * D_);
        const int   xld   = (l == 0) ? D_ : F_;
        const long  xbs   = (l == 0) ? (long)S_ * D_ : (long)S_ * F_;
        const float* XTp  = (l == 0) ? X0T : XT;

        // GEMM1: g_Ax = adj_i @ X + X     (A=adj K-major, B=X^T K-major)
        mma_gemm<0><<<dim3(4, 4, B_), 256, SMEM_SZ>>>(
            adj + (long)i * B_ * S_ * S_, XTp, Ax,
            S_, S_, S_, D_,
            (long)S_ * S_, (long)D_ * S_, (long)S_ * D_,
            Xrow, xld, xbs,
            nullptr, 0.f,
            nullptr, 0);

        // GEMM2: fin[..,idx] = relu((g_Ax @ W_idx^T + 2b) / denom)
        mma_gemm<1><<<dim3(4, 4, B_), 256, SMEM_SZ>>>(
            Ax, Wg + (long)idx * D_ * D_, fin + (long)idx * D_,
            D_, D_, D_, F_,
            (long)S_ * D_, 0, (long)S_ * F_,
            nullptr, 0, 0,
            bg + (long)idx * D_, 2.0f,
            den + (long)i * B_ * S_, S_);

        // layer-0 output -> transposed copy for layer-1's GEMM1
        if (l == 0)
            transpose_kernel<<<dim3(16, 16, B_), dim3(32, 8)>>>(
                fin + (long)idx * D_, F_, (long)S_ * F_, XT);
    }

    // Final: out = fin @ W_out^T + b_out + x0   (M = B*S = 8192)
    mma_gemm<2><<<dim3(4, 64, 1), 256, SMEM_SZ>>>(
        fin, Wo, out,
        F_, F_, F_, D_,
        0, 0, 0,
        x0, D_, 0,
        bo, 1.0f,
        nullptr, 0);
}

// round 4
// speedup vs baseline: 1.9533x; 1.1269x over previous
#include <cuda_runtime.h>
#include <cstdint>

#define H_ 3
#define L_ 2
#define B_ 16
#define S_ 512
#define D_ 512
#define F_ (H_ * L_ * D_)   // 3072

// Scratch (no cudaMalloc allowed)
__device__ float g_Ax[(size_t)H_ * B_ * S_ * D_];     // 50 MB  [h][b][s][d]
__device__ float g_final[(size_t)B_ * S_ * F_];       // 96 MB  [b][s][h*l*d]
__device__ float g_denom[H_ * B_ * S_];               // 96 KB
__device__ float g_XT[(size_t)H_ * B_ * D_ * S_];     // 50 MB  [h][b][d][s]
__device__ float g_X0T[(size_t)B_ * D_ * S_];         // 16 MB  [b][d][s]
__device__ float g_adjR[(size_t)H_ * B_ * S_ * S_];   // 50 MB  tf32-rounded adj
__device__ float g_WgR[(size_t)H_ * L_ * D_ * D_];    // 6 MB
__device__ float g_WoR[(size_t)D_ * F_];              // 6 MB

// ---------------------------------------------------------------------------
__device__ __forceinline__ uint32_t smem_u32(const void* p) {
    uint32_t a;
    asm("{ .reg .u64 t; cvta.to.shared.u64 t, %1; cvt.u32.u64 %0, t; }" : "=r"(a) : "l"(p));
    return a;
}
__device__ __forceinline__ float rtf(float x) {
    uint32_t r;
    asm("cvt.rna.tf32.f32 %0, %1;" : "=r"(r) : "f"(x));
    return __uint_as_float(r);
}
#define CP_ASYNC16(dst, src) \
    asm volatile("cp.async.cg.shared.global [%0], [%1], 16;" :: "r"(dst), "l"(src))
#define CP_COMMIT() asm volatile("cp.async.commit_group;")
#define CP_WAIT(n)  asm volatile("cp.async.wait_group %0;" :: "n"(n))

#define LDSM4(r0, r1, r2, r3, addr) \
    asm volatile("ldmatrix.sync.aligned.m8n8.x4.shared.b16 {%0,%1,%2,%3}, [%4];" \
        : "=r"(r0), "=r"(r1), "=r"(r2), "=r"(r3) : "r"(addr))

#define MMA_TF32(c, a, b0, b1) \
    asm volatile("mma.sync.aligned.m16n8k8.row.col.f32.tf32.tf32.f32 " \
        "{%0,%1,%2,%3}, {%4,%5,%6,%7}, {%8,%9}, {%0,%1,%2,%3};" \
        : "+f"((c)[0]), "+f"((c)[1]), "+f"((c)[2]), "+f"((c)[3]) \
        : "r"((a)[0]), "r"((a)[1]), "r"((a)[2]), "r"((a)[3]), \
          "r"(b0), "r"(b1))

// ---------------------------------------------------------------------------
// Per row (h,b,s): den = 1 + sum_t adj[..t] (exact), adjR[..t] = tf32(adj[..t])
// ---------------------------------------------------------------------------
__global__ void denom_round_kernel(const float* __restrict__ adj,
                                   float* __restrict__ den,
                                   float* __restrict__ adjR)
{
    int gw = (blockIdx.x * blockDim.x + threadIdx.x) >> 5;
    int lane = threadIdx.x & 31;
    if (gw >= H_ * B_ * S_) return;
    const float4* p = (const float4*)(adj + (long)gw * S_);
    float4* q = (float4*)(adjR + (long)gw * S_);
    float s = 0.f;
    #pragma unroll 2
    for (int i = lane; i < S_ / 4; i += 32) {
        float4 v = p[i];
        s += v.x + v.y + v.z + v.w;
        float4 r = {rtf(v.x), rtf(v.y), rtf(v.z), rtf(v.w)};
        q[i] = r;
    }
    #pragma unroll
    for (int o = 16; o > 0; o >>= 1) s += __shfl_xor_sync(0xffffffffu, s, o);
    if (lane == 0) den[gw] = s + 1.0f;
}

__global__ void roundcopy_kernel(const float* __restrict__ src,
                                 float* __restrict__ dst, int n4)
{
    int i = blockIdx.x * blockDim.x + threadIdx.x;
    if (i >= n4) return;
    float4 v = ((const float4*)src)[i];
    float4 r = {rtf(v.x), rtf(v.y), rtf(v.z), rtf(v.w)};
    ((float4*)dst)[i] = r;
}

// ---------------------------------------------------------------------------
// XT[h][b][d][s] = tf32( X[(h,b)-indexed][s][d] )
// ---------------------------------------------------------------------------
__global__ void transpose_kernel(const float* __restrict__ X, int ldx,
                                 long xHead, long xBatch,
                                 float* __restrict__ XT, long tHead)
{
    __shared__ float t[32][33];
    int z = blockIdx.z;
    int hz = z >> 4, bz = z & 15;
    int s0 = blockIdx.x * 32, d0 = blockIdx.y * 32;
    const float* Xb = X + (long)hz * xHead + (long)bz * xBatch;
    float* Tb = XT + (long)hz * tHead + (long)bz * D_ * S_;
    int tx = threadIdx.x, ty = threadIdx.y;  // 32 x 8
    #pragma unroll
    for (int i = 0; i < 32; i += 8)
        t[ty + i][tx] = rtf(Xb[(long)(s0 + ty + i) * ldx + d0 + tx]);
    __syncthreads();
    #pragma unroll
    for (int i = 0; i < 32; i += 8)
        Tb[(long)(d0 + ty + i) * S_ + s0 + tx] = t[tx][ty + i];
}

// ---------------------------------------------------------------------------
// TF32 mma.sync GEMM, operands pre-rounded to tf32 (no cvt in the hot loop).
// C[M,N] = A[M,K] (K-major) * B[N,K]^T (K-major)
// z encodes (head = z>>4, batch = z&15).
// MODE 0: C = tf32(acc + epi[m][n])
// MODE 1: C = tf32(relu((acc + biasScale*bias[n]) / denom[z,m]))
// MODE 2: C = acc + bias[n] + epi[m][n]     (full fp32 output)
// ---------------------------------------------------------------------------
constexpr int BM = 128, BN = 128, BK = 32;
constexpr int LDSROW = 36;                        // floats; conflict-free LDS/LDSM
constexpr int STAGE_FLOATS = 2 * BM * LDSROW;     // 9216
constexpr int STAGE_BYTES = STAGE_FLOATS * 4;     // 36864
constexpr int SMEM_SZ = 2 * STAGE_BYTES;          // 73728

template <int MODE>
__global__ __launch_bounds__(256, 2)
void mma_gemm(const float* __restrict__ A, const float* __restrict__ Bm,
              float* __restrict__ C,
              int K, int lda, int ldb, int ldc,
              long aHead, long aBatch, long bHead, long bBatch,
              long cHead, long cBatch,
              const float* __restrict__ epi, int epiLd, long epiHead, long epiBatch,
              const float* __restrict__ bias, long biasHead, float biasScale,
              const float* __restrict__ denom, int denomStride)
{
    extern __shared__ float smemf[];
    const int tid = threadIdx.x;
    const int wid = tid >> 5, lane = tid & 31;
    const int bx = blockIdx.x, by = blockIdx.y, z = blockIdx.z;
    const int hz = z >> 4, bz = z & 15;

    const uint32_t sbase = smem_u32(smemf);

    const float* Ab = A + (long)hz * aHead + (long)bz * aBatch + (long)(by * BM) * lda;
    const float* Bb = Bm + (long)hz * bHead + (long)bz * bBatch + (long)(bx * BN) * ldb;

    // cp.async mapping: 2 threads per row, 4 x 16B chunks each
    const int ldrow = tid >> 1;
    const int ldc0  = (tid & 1) * 16;

    auto load_stage = [&](int s, int kt) {
        const long k0 = (long)kt * BK + ldc0;
        const float* ag = Ab + (long)ldrow * lda + k0;
        const float* bg = Bb + (long)ldrow * ldb + k0;
        uint32_t da = sbase + (uint32_t)(s * STAGE_FLOATS + ldrow * LDSROW + ldc0) * 4u;
        uint32_t db = da + (uint32_t)(BM * LDSROW) * 4u;
        #pragma unroll
        for (int i = 0; i < 4; ++i) {
            CP_ASYNC16(da + i * 16u, ag + i * 4);
            CP_ASYNC16(db + i * 16u, bg + i * 4);
        }
    };

    // warp tiling: 2 (m) x 4 (n); each warp 64x32
    const int m0 = (wid & 1) * 64;
    const int n0 = (wid >> 1) * 32;
    const int lq = lane >> 2;
    const int lr = lane & 3;

    // ldmatrix per-lane base addresses (stage 0, ks = 0)
    // A x4: matrices {rows0-7 c0-3, rows8-15 c0-3, rows0-7 c4-7, rows8-15 c4-7}
    const uint32_t aAddr0 = sbase
        + (uint32_t)((m0 + ((lane >> 3) & 1) * 8 + (lane & 7)) * LDSROW) * 4u
        + (uint32_t)(lane >> 4) * 16u;
    // B x4 (two n8 tiles): matrices {r0-7 c0-3, r0-7 c4-7, r8-15 c0-3, r8-15 c4-7}
    const uint32_t bAddr0 = sbase + (uint32_t)(BM * LDSROW) * 4u
        + (uint32_t)((n0 + (lane >> 4) * 8 + (lane & 7)) * LDSROW) * 4u
        + (uint32_t)((lane >> 3) & 1) * 16u;

    float c[4][4][4];
    #pragma unroll
    for (int mi = 0; mi < 4; ++mi)
        #pragma unroll
        for (int ni = 0; ni < 4; ++ni)
            #pragma unroll
            for (int j = 0; j < 4; ++j) c[mi][ni][j] = 0.f;

    const int numK = K >> 5;

    load_stage(0, 0);
    CP_COMMIT();

    for (int kt = 0; kt < numK; ++kt) {
        const int s = kt & 1;
        if (kt + 1 < numK) {
            load_stage(s ^ 1, kt + 1);
            CP_COMMIT();
            CP_WAIT(1);
        } else {
            CP_WAIT(0);
        }
        __syncthreads();

        const uint32_t sOff = (uint32_t)s * STAGE_BYTES;
        #pragma unroll
        for (int ks = 0; ks < 4; ++ks) {
            const uint32_t kOff = sOff + (uint32_t)ks * 32u;
            uint32_t a[4][4], b[2][4];
            #pragma unroll
            for (int mi = 0; mi < 4; ++mi)
                LDSM4(a[mi][0], a[mi][1], a[mi][2], a[mi][3],
                      aAddr0 + kOff + (uint32_t)mi * (16u * LDSROW * 4u));
            #pragma unroll
            for (int p = 0; p < 2; ++p)
                LDSM4(b[p][0], b[p][1], b[p][2], b[p][3],
                      bAddr0 + kOff + (uint32_t)p * (16u * LDSROW * 4u));
            #pragma unroll
            for (int mi = 0; mi < 4; ++mi)
                #pragma unroll
                for (int ni = 0; ni < 4; ++ni)
                    MMA_TF32(c[mi][ni], a[mi], b[ni >> 1][(ni & 1) * 2],
                             b[ni >> 1][(ni & 1) * 2 + 1]);
        }
        __syncthreads();
    }

    // ---------------- epilogue ----------------
    float* Cb = C + (long)hz * cHead + (long)bz * cBatch;
    const float* Eb = (MODE == 0 || MODE == 2)
        ? (epi + (long)hz * epiHead + (long)bz * epiBatch) : nullptr;
    const float* biasP = (MODE == 1 || MODE == 2) ? (bias + (long)hz * biasHead) : nullptr;

    #pragma unroll
    for (int mi = 0; mi < 4; ++mi) {
        const int r0 = by * BM + m0 + mi * 16 + lq;
        float invd0 = 1.f, invd1 = 1.f;
        if (MODE == 1) {
            invd0 = 1.0f / denom[(long)z * denomStride + r0];
            invd1 = 1.0f / denom[(long)z * denomStride + r0 + 8];
        }
        #pragma unroll
        for (int ni = 0; ni < 4; ++ni) {
            const int col = bx * BN + n0 + ni * 8 + 2 * lr;
            float v00 = c[mi][ni][0], v01 = c[mi][ni][1];
            float v10 = c[mi][ni][2], v11 = c[mi][ni][3];
            if (MODE == 1) {
                const float b0 = biasScale * biasP[col];
                const float b1 = biasScale * biasP[col + 1];
                v00 = rtf(fmaxf((v00 + b0) * invd0, 0.f));
                v01 = rtf(fmaxf((v01 + b1) * invd0, 0.f));
                v10 = rtf(fmaxf((v10 + b0) * invd1, 0.f));
                v11 = rtf(fmaxf((v11 + b1) * invd1, 0.f));
            } else if (MODE == 0) {
                const float2 e0 = *(const float2*)(Eb + (long)r0 * epiLd + col);
                const float2 e1 = *(const float2*)(Eb + (long)(r0 + 8) * epiLd + col);
                v00 = rtf(v00 + e0.x); v01 = rtf(v01 + e0.y);
                v10 = rtf(v10 + e1.x); v11 = rtf(v11 + e1.y);
            } else {  // MODE 2: exact fp32 output
                const float2 e0 = *(const float2*)(Eb + (long)r0 * epiLd + col);
                const float2 e1 = *(const float2*)(Eb + (long)(r0 + 8) * epiLd + col);
                const float b0 = biasP[col], b1 = biasP[col + 1];
                v00 += e0.x + b0; v01 += e0.y + b1;
                v10 += e1.x + b0; v11 += e1.y + b1;
            }
            float2 w0 = {v00, v01}, w1 = {v10, v11};
            *(float2*)(Cb + (long)r0 * ldc + col) = w0;
            *(float2*)(Cb + (long)(r0 + 8) * ldc + col) = w1;
        }
    }
}

// ---------------------------------------------------------------------------
extern "C" void kernel_launch(void* const* d_in, const int* in_sizes, int n_in,
                              void* d_out, int out_size)
{
    const float* adj = (const float*)d_in[0];   // [H,B,S,S]
    const float* x0  = (const float*)d_in[1];   // [B,S,D]
    const float* Wg  = (const float*)d_in[4];   // [H*L, D, D]
    const float* bg  = (const float*)d_in[5];   // [H*L, D]
    const float* Wo  = (const float*)d_in[6];   // [D, F]
    const float* bo  = (const float*)d_in[7];   // [D]
    float* out = (float*)d_out;                 // [B,S,D]

    float *Ax, *fin, *den, *XT, *X0T, *adjR, *WgR, *WoR;
    cudaGetSymbolAddress((void**)&Ax,   g_Ax);
    cudaGetSymbolAddress((void**)&fin,  g_final);
    cudaGetSymbolAddress((void**)&den,  g_denom);
    cudaGetSymbolAddress((void**)&XT,   g_XT);
    cudaGetSymbolAddress((void**)&X0T,  g_X0T);
    cudaGetSymbolAddress((void**)&adjR, g_adjR);
    cudaGetSymbolAddress((void**)&WgR,  g_WgR);
    cudaGetSymbolAddress((void**)&WoR,  g_WoR);

    cudaFuncSetAttribute(mma_gemm<0>, cudaFuncAttributeMaxDynamicSharedMemorySize, SMEM_SZ);
    cudaFuncSetAttribute(mma_gemm<1>, cudaFuncAttributeMaxDynamicSharedMemorySize, SMEM_SZ);
    cudaFuncSetAttribute(mma_gemm<2>, cudaFuncAttributeMaxDynamicSharedMemorySize, SMEM_SZ);

    // ---- prep: denom + tf32-rounded copies of all static operands ----
    denom_round_kernel<<<(H_ * B_ * S_) / 8, 256>>>(adj, den, adjR);
    roundcopy_kernel<<<(H_ * L_ * D_ * D_ / 4 + 255) / 256, 256>>>(Wg, WgR, H_ * L_ * D_ * D_ / 4);
    roundcopy_kernel<<<(D_ * F_ / 4 + 255) / 256, 256>>>(Wo, WoR, D_ * F_ / 4);
    transpose_kernel<<<dim3(16, 16, B_), dim3(32, 8)>>>(x0, D_, 0, (long)S_ * D_, X0T, 0);

    const long SS = (long)S_ * S_, SD = (long)S_ * D_, SF = (long)S_ * F_;
    const long DS = (long)D_ * S_, DD = (long)D_ * D_;

    for (int l = 0; l < L_; ++l) {
        // GEMM1 (all heads): Ax[h] = adj[h] @ X + X
        if (l == 0) {
            mma_gemm<0><<<dim3(4, 4, H_ * B_), 256, SMEM_SZ>>>(
                adjR, X0T, Ax,
                S_, S_, S_, D_,
                (long)B_ * SS, SS, 0, DS, (long)B_ * SD, SD,
                x0, D_, 0, SD,
                nullptr, 0, 0.f,
                nullptr, 0);
        } else {
            mma_gemm<0><<<dim3(4, 4, H_ * B_), 256, SMEM_SZ>>>(
                adjR, XT, Ax,
                S_, S_, S_, D_,
                (long)B_ * SS, SS, (long)B_ * DS, DS, (long)B_ * SD, SD,
                fin, F_, (long)L_ * D_, SF,     // epi = previous layer output cols
                nullptr, 0, 0.f,
                nullptr, 0);
        }

        // GEMM2 (all heads): fin[.., (h*L+l)*D ..] = relu((Ax[h] @ Wg^T + 2b)/den)
        mma_gemm<1><<<dim3(4, 4, H_ * B_), 256, SMEM_SZ>>>(
            Ax, WgR + (long)l * DD, fin + (long)l * D_,
            D_, D_, D_, F_,
            (long)B_ * SD, SD, (long)L_ * DD, 0, (long)L_ * D_, SF,
            nullptr, 0, 0, 0,
            bg + (long)l * D_, (long)L_ * D_, 2.0f,
            den, S_);

        // layer-0 outputs -> transposed (tf32) for layer-1 GEMM1 B operand
        if (l == 0)
            transpose_kernel<<<dim3(16, 16, H_ * B_), dim3(32, 8)>>>(
                fin, F_, (long)L_ * D_, SF, XT, (long)B_ * DS);
    }

    // Final: out = fin @ Wo^T + bo + x0   (M = B*S = 8192, K = F)
    mma_gemm<2><<<dim3(4, 64, 1), 256, SMEM_SZ>>>(
        fin, WoR, out,
        F_, F_, F_, D_,
        0, 0, 0, 0, 0, 0,
        x0, D_, 0, 0,
        bo, 0, 1.0f,
        nullptr, 0);
}

// round 6
// speedup vs baseline: 3.5162x; 1.8002x over previous
#include <cuda_runtime.h>
#include <cuda_fp16.h>
#include <cstdint>

#define H_ 3
#define L_ 2
#define B_ 16
#define S_ 512
#define D_ 512
#define F_ (H_ * L_ * D_)   // 3072

// Scratch (no cudaMalloc allowed) — fp16 operand buffers
__device__ __align__(16) __half g_adjH[(size_t)H_ * B_ * S_ * S_];  // 25 MB
__device__ __align__(16) __half g_AxH[(size_t)H_ * B_ * S_ * D_];   // 25 MB
__device__ __align__(16) __half g_finH[(size_t)B_ * S_ * F_];       // 50 MB
__device__ __align__(16) __half g_XTH[(size_t)H_ * B_ * D_ * S_];   // 25 MB
__device__ __align__(16) __half g_X0TH[(size_t)B_ * D_ * S_];       // 8 MB
__device__ __align__(16) __half g_WgH[(size_t)H_ * L_ * D_ * D_];   // 3 MB
__device__ __align__(16) __half g_WoH[(size_t)D_ * F_];             // 3 MB
__device__ float g_denom[H_ * B_ * S_];                             // 96 KB

// ---------------------------------------------------------------------------
__device__ __forceinline__ uint32_t smem_u32(const void* p) {
    uint32_t a;
    asm("{ .reg .u64 t; cvta.to.shared.u64 t, %1; cvt.u32.u64 %0, t; }" : "=r"(a) : "l"(p));
    return a;
}
#define CP_ASYNC16(dst, src) \
    asm volatile("cp.async.cg.shared.global [%0], [%1], 16;" :: "r"(dst), "l"(src))
#define CP_COMMIT() asm volatile("cp.async.commit_group;")
#define CP_WAIT(n)  asm volatile("cp.async.wait_group %0;" :: "n"(n))

#define LDSM4(r0, r1, r2, r3, addr) \
    asm volatile("ldmatrix.sync.aligned.m8n8.x4.shared.b16 {%0,%1,%2,%3}, [%4];" \
        : "=r"(r0), "=r"(r1), "=r"(r2), "=r"(r3) : "r"(addr))

#define MMA_F16(c, a, b0, b1) \
    asm volatile("mma.sync.aligned.m16n8k16.row.col.f32.f16.f16.f32 " \
        "{%0,%1,%2,%3}, {%4,%5,%6,%7}, {%8,%9}, {%0,%1,%2,%3};" \
        : "+f"((c)[0]), "+f"((c)[1]), "+f"((c)[2]), "+f"((c)[3]) \
        : "r"((a)[0]), "r"((a)[1]), "r"((a)[2]), "r"((a)[3]), \
          "r"(b0), "r"(b1))

__device__ __forceinline__ __half toh(float x)  { return __float2half_rn(x); }
__device__ __forceinline__ __half toh(__half x) { return x; }

// ---------------------------------------------------------------------------
// Per row (h,b,s): den = 1 + sum_t adj (exact fp32), adjH = half(adj)
// ---------------------------------------------------------------------------
__global__ void denom_round_kernel(const float* __restrict__ adj,
                                   float* __restrict__ den,
                                   __half* __restrict__ adjH)
{
    int gw = (blockIdx.x * blockDim.x + threadIdx.x) >> 5;
    int lane = threadIdx.x & 31;
    if (gw >= H_ * B_ * S_) return;
    const float4* p = (const float4*)(adj + (long)gw * S_);
    __half2* q = (__half2*)(adjH + (long)gw * S_);
    float s = 0.f;
    #pragma unroll 2
    for (int i = lane; i < S_ / 4; i += 32) {
        float4 v = p[i];
        s += v.x + v.y + v.z + v.w;
        q[2 * i]     = __floats2half2_rn(v.x, v.y);
        q[2 * i + 1] = __floats2half2_rn(v.z, v.w);
    }
    #pragma unroll
    for (int o = 16; o > 0; o >>= 1) s += __shfl_xor_sync(0xffffffffu, s, o);
    if (lane == 0) den[gw] = s + 1.0f;
}

__global__ void roundcopy_half(const float* __restrict__ src,
                               __half* __restrict__ dst, int n4)
{
    int i = blockIdx.x * blockDim.x + threadIdx.x;
    if (i >= n4) return;
    float4 v = ((const float4*)src)[i];
    ((__half2*)dst)[2 * i]     = __floats2half2_rn(v.x, v.y);
    ((__half2*)dst)[2 * i + 1] = __floats2half2_rn(v.z, v.w);
}

// ---------------------------------------------------------------------------
// XT[h][b][d][s] = half( X[...][s][d] )
// ---------------------------------------------------------------------------
template <typename T>
__global__ void transpose_kernel(const T* __restrict__ X, int ldx,
                                 long xHead, long xBatch,
                                 __half* __restrict__ XT, long tHead)
{
    __shared__ __half t[32][33];
    int z = blockIdx.z;
    int hz = z >> 4, bz = z & 15;
    int s0 = blockIdx.x * 32, d0 = blockIdx.y * 32;
    const T* Xb = X + (long)hz * xHead + (long)bz * xBatch;
    __half* Tb = XT + (long)hz * tHead + (long)bz * D_ * S_;
    int tx = threadIdx.x, ty = threadIdx.y;  // 32 x 8
    #pragma unroll
    for (int i = 0; i < 32; i += 8)
        t[ty + i][tx] = toh(Xb[(long)(s0 + ty + i) * ldx + d0 + tx]);
    __syncthreads();
    #pragma unroll
    for (int i = 0; i < 32; i += 8)
        Tb[(long)(d0 + ty + i) * S_ + s0 + tx] = t[tx][ty + i];
}

// ---------------------------------------------------------------------------
// FP16 mma.sync GEMM (fp32 accum): C[M,N] = A[M,K] * B[N,K]^T, K-major halves.
// z encodes (head = z>>4, batch = z&15).
// MODE 0: Chalf = acc + epi[m][n]             (epi fp32 or fp16 per EPI_HALF)
// MODE 1: Chalf = relu((acc + biasScale*bias[n]) / denom[z,m])
// MODE 2: Cfloat = acc + bias[n] + epi[m][n]  (epi fp32)
// ---------------------------------------------------------------------------
constexpr int BM = 128, BN = 128, BK = 64;        // BK in halves (128 bytes)
constexpr int LDSROW = 72;                        // halves; 144B stride -> conflict-free
constexpr int STAGE_HALVES = 2 * BM * LDSROW;     // A + B = 18432
constexpr int STAGE_BYTES = STAGE_HALVES * 2;     // 36864
constexpr int SMEM_SZ = 2 * STAGE_BYTES;          // 73728

template <int MODE, bool EPI_HALF>
__global__ __launch_bounds__(256, 2)
void mma_gemm(const __half* __restrict__ A, const __half* __restrict__ Bm,
              void* __restrict__ C,
              int K, int lda, int ldb, int ldc,
              long aHead, long aBatch, long bHead, long bBatch,
              long cHead, long cBatch,
              const void* __restrict__ epi, int epiLd, long epiHead, long epiBatch,
              const float* __restrict__ bias, long biasHead, float biasScale,
              const float* __restrict__ denom, int denomStride)
{
    extern __shared__ char smemc[];
    const int tid = threadIdx.x;
    const int wid = tid >> 5, lane = tid & 31;
    const int bx = blockIdx.x, by = blockIdx.y, z = blockIdx.z;
    const int hz = z >> 4, bz = z & 15;

    const uint32_t sbase = smem_u32(smemc);

    const __half* Ab = A + (long)hz * aHead + (long)bz * aBatch + (long)(by * BM) * lda;
    const __half* Bb = Bm + (long)hz * bHead + (long)bz * bBatch + (long)(bx * BN) * ldb;

    // cp.async: 2 threads per 128B row, 4 x 16B chunks each
    const int ldrow = tid >> 1;
    const int ldh0  = (tid & 1) * 32;      // half offset within row

    auto load_stage = [&](int s, int kt) {
        const long k0 = (long)kt * BK + ldh0;
        const __half* ag = Ab + (long)ldrow * lda + k0;
        const __half* bg = Bb + (long)ldrow * ldb + k0;
        uint32_t da = sbase + (uint32_t)(s * STAGE_BYTES)
                    + (uint32_t)(ldrow * LDSROW + ldh0) * 2u;
        uint32_t db = da + (uint32_t)(BM * LDSROW) * 2u;
        #pragma unroll
        for (int i = 0; i < 4; ++i) {
            CP_ASYNC16(da + i * 16u, ag + i * 8);
            CP_ASYNC16(db + i * 16u, bg + i * 8);
        }
    };

    // warp tiling: 2 (m) x 4 (n); each warp 64x32
    const int m0 = (wid & 1) * 64;
    const int n0 = (wid >> 1) * 32;
    const int lq = lane >> 2;
    const int lr = lane & 3;

    // ldmatrix base addresses (stage 0, ks = 0)
    const uint32_t aAddr0 = sbase
        + (uint32_t)((m0 + ((lane >> 3) & 1) * 8 + (lane & 7)) * LDSROW) * 2u
        + (uint32_t)(lane >> 4) * 16u;
    const uint32_t bAddr0 = sbase + (uint32_t)(BM * LDSROW) * 2u
        + (uint32_t)((n0 + (lane >> 4) * 8 + (lane & 7)) * LDSROW) * 2u
        + (uint32_t)((lane >> 3) & 1) * 16u;

    float c[4][4][4];
    #pragma unroll
    for (int mi = 0; mi < 4; ++mi)
        #pragma unroll
        for (int ni = 0; ni < 4; ++ni)
            #pragma unroll
            for (int j = 0; j < 4; ++j) c[mi][ni][j] = 0.f;

    const int numK = K >> 6;

    load_stage(0, 0);
    CP_COMMIT();

    for (int kt = 0; kt < numK; ++kt) {
        const int s = kt & 1;
        if (kt + 1 < numK) {
            load_stage(s ^ 1, kt + 1);
            CP_COMMIT();
            CP_WAIT(1);
        } else {
            CP_WAIT(0);
        }
        __syncthreads();

        const uint32_t sOff = (uint32_t)s * STAGE_BYTES;
        #pragma unroll
        for (int ks = 0; ks < 4; ++ks) {          // k16 steps within BK=64
            const uint32_t kOff = sOff + (uint32_t)ks * 32u;   // 16 halves
            uint32_t a[4][4], b[2][4];
            #pragma unroll
            for (int mi = 0; mi < 4; ++mi)
                LDSM4(a[mi][0], a[mi][1], a[mi][2], a[mi][3],
                      aAddr0 + kOff + (uint32_t)mi * (16u * LDSROW * 2u));
            #pragma unroll
            for (int p = 0; p < 2; ++p)
                LDSM4(b[p][0], b[p][1], b[p][2], b[p][3],
                      bAddr0 + kOff + (uint32_t)p * (16u * LDSROW * 2u));
            #pragma unroll
            for (int mi = 0; mi < 4; ++mi)
                #pragma unroll
                for (int ni = 0; ni < 4; ++ni)
                    MMA_F16(c[mi][ni], a[mi], b[ni >> 1][(ni & 1) * 2],
                            b[ni >> 1][(ni & 1) * 2 + 1]);
        }
        __syncthreads();
    }

    // ---------------- epilogue ----------------
    const float* biasP = (MODE == 1 || MODE == 2) ? (bias + (long)hz * biasHead) : nullptr;

    #pragma unroll
    for (int mi = 0; mi < 4; ++mi) {
        const int r0 = by * BM + m0 + mi * 16 + lq;
        float invd0 = 1.f, invd1 = 1.f;
        if (MODE == 1) {
            invd0 = 1.0f / denom[(long)z * denomStride + r0];
            invd1 = 1.0f / denom[(long)z * denomStride + r0 + 8];
        }
        #pragma unroll
        for (int ni = 0; ni < 4; ++ni) {
            const int col = bx * BN + n0 + ni * 8 + 2 * lr;
            float v00 = c[mi][ni][0], v01 = c[mi][ni][1];
            float v10 = c[mi][ni][2], v11 = c[mi][ni][3];
            if (MODE == 0) {
                if (EPI_HALF) {
                    const __half* Eb = (const __half*)epi
                        + (long)hz * epiHead + (long)bz * epiBatch;
                    float2 e0 = __half22float2(*(const __half2*)(Eb + (long)r0 * epiLd + col));
                    float2 e1 = __half22float2(*(const __half2*)(Eb + (long)(r0 + 8) * epiLd + col));
                    v00 += e0.x; v01 += e0.y; v10 += e1.x; v11 += e1.y;
                } else {
                    const float* Eb = (const float*)epi
                        + (long)hz * epiHead + (long)bz * epiBatch;
                    float2 e0 = *(const float2*)(Eb + (long)r0 * epiLd + col);
                    float2 e1 = *(const float2*)(Eb + (long)(r0 + 8) * epiLd + col);
                    v00 += e0.x; v01 += e0.y; v10 += e1.x; v11 += e1.y;
                }
                __half* Cb = (__half*)C + (long)hz * cHead + (long)bz * cBatch;
                *(__half2*)(Cb + (long)r0 * ldc + col)       = __floats2half2_rn(v00, v01);
                *(__half2*)(Cb + (long)(r0 + 8) * ldc + col) = __floats2half2_rn(v10, v11);
            } else if (MODE == 1) {
                const float b0 = biasScale * biasP[col];
                const float b1 = biasScale * biasP[col + 1];
                v00 = fmaxf((v00 + b0) * invd0, 0.f);
                v01 = fmaxf((v01 + b1) * invd0, 0.f);
                v10 = fmaxf((v10 + b0) * invd1, 0.f);
                v11 = fmaxf((v11 + b1) * invd1, 0.f);
                __half* Cb = (__half*)C + (long)hz * cHead + (long)bz * cBatch;
                *(__half2*)(Cb + (long)r0 * ldc + col)       = __floats2half2_rn(v00, v01);
                *(__half2*)(Cb + (long)(r0 + 8) * ldc + col) = __floats2half2_rn(v10, v11);
            } else {  // MODE 2: fp32 output, fp32 epi (residual) + bias
                const float* Eb = (const float*)epi;
                float2 e0 = *(const float2*)(Eb + (long)r0 * epiLd + col);
                float2 e1 = *(const float2*)(Eb + (long)(r0 + 8) * epiLd + col);
                const float b0 = biasP[col], b1 = biasP[col + 1];
                v00 += e0.x + b0; v01 += e0.y + b1;
                v10 += e1.x + b0; v11 += e1.y + b1;
                float* Cb = (float*)C;
                float2 w0 = {v00, v01}, w1 = {v10, v11};
                *(float2*)(Cb + (long)r0 * ldc + col) = w0;
                *(float2*)(Cb + (long)(r0 + 8) * ldc + col) = w1;
            }
        }
    }
}

// ---------------------------------------------------------------------------
extern "C" void kernel_launch(void* const* d_in, const int* in_sizes, int n_in,
                              void* d_out, int out_size)
{
    const float* adj = (const float*)d_in[0];   // [H,B,S,S]
    const float* x0  = (const float*)d_in[1];   // [B,S,D]
    const float* Wg  = (const float*)d_in[4];   // [H*L, D, D]
    const float* bg  = (const float*)d_in[5];   // [H*L, D]
    const float* Wo  = (const float*)d_in[6];   // [D, F]
    const float* bo  = (const float*)d_in[7];   // [D]
    float* out = (float*)d_out;                 // [B,S,D]

    __half *adjH, *AxH, *finH, *XTH, *X0TH, *WgH, *WoH;
    float* den;
    cudaGetSymbolAddress((void**)&adjH, g_adjH);
    cudaGetSymbolAddress((void**)&AxH,  g_AxH);
    cudaGetSymbolAddress((void**)&finH, g_finH);
    cudaGetSymbolAddress((void**)&XTH,  g_XTH);
    cudaGetSymbolAddress((void**)&X0TH, g_X0TH);
    cudaGetSymbolAddress((void**)&WgH,  g_WgH);
    cudaGetSymbolAddress((void**)&WoH,  g_WoH);
    cudaGetSymbolAddress((void**)&den,  g_denom);

    cudaFuncSetAttribute(mma_gemm<0, false>, cudaFuncAttributeMaxDynamicSharedMemorySize, SMEM_SZ);
    cudaFuncSetAttribute(mma_gemm<0, true>,  cudaFuncAttributeMaxDynamicSharedMemorySize, SMEM_SZ);
    cudaFuncSetAttribute(mma_gemm<1, false>, cudaFuncAttributeMaxDynamicSharedMemorySize, SMEM_SZ);
    cudaFuncSetAttribute(mma_gemm<2, false>, cudaFuncAttributeMaxDynamicSharedMemorySize, SMEM_SZ);

    // ---- prep: denom + fp16 operand copies ----
    denom_round_kernel<<<(H_ * B_ * S_) / 8, 256>>>(adj, den, adjH);
    roundcopy_half<<<(H_ * L_ * D_ * D_ / 4 + 255) / 256, 256>>>(Wg, WgH, H_ * L_ * D_ * D_ / 4);
    roundcopy_half<<<(D_ * F_ / 4 + 255) / 256, 256>>>(Wo, WoH, D_ * F_ / 4);
    transpose_kernel<float><<<dim3(16, 16, B_), dim3(32, 8)>>>(
        x0, D_, 0, (long)S_ * D_, X0TH, 0);

    const long SS = (long)S_ * S_, SD = (long)S_ * D_, SF = (long)S_ * F_;
    const long DS = (long)D_ * S_, DD = (long)D_ * D_;

    for (int l = 0; l < L_; ++l) {
        // GEMM1 (all heads): AxH[h] = adj[h] @ X + X
        if (l == 0) {
            mma_gemm<0, false><<<dim3(4, 4, H_ * B_), 256, SMEM_SZ>>>(
                adjH, X0TH, AxH,
                S_, S_, S_, D_,
                (long)B_ * SS, SS, 0, DS, (long)B_ * SD, SD,
                x0, D_, 0, SD,
                nullptr, 0, 0.f,
                nullptr, 0);
        } else {
            mma_gemm<0, true><<<dim3(4, 4, H_ * B_), 256, SMEM_SZ>>>(
                adjH, XTH, AxH,
                S_, S_, S_, D_,
                (long)B_ * SS, SS, (long)B_ * DS, DS, (long)B_ * SD, SD,
                finH, F_, (long)L_ * D_, SF,   // epi = prev layer output (fp16)
                nullptr, 0, 0.f,
                nullptr, 0);
        }

        // GEMM2 (all heads): finH[.., (h*L+l)*D ..] = relu((AxH @ Wg^T + 2b)/den)
        mma_gemm<1, false><<<dim3(4, 4, H_ * B_), 256, SMEM_SZ>>>(
            AxH, WgH + (long)l * DD, finH + (long)l * D_,
            D_, D_, D_, F_,
            (long)B_ * SD, SD, (long)L_ * DD, 0, (long)L_ * D_, SF,
            nullptr, 0, 0, 0,
            bg + (long)l * D_, (long)L_ * D_, 2.0f,
            den, S_);

        // layer-0 outputs -> transposed fp16 for layer-1 GEMM1 B operand
        if (l == 0)
            transpose_kernel<__half><<<dim3(16, 16, H_ * B_), dim3(32, 8)>>>(
                finH, F_, (long)L_ * D_, SF, XTH, (long)B_ * DS);
    }

    // Final: out = finH @ Wo^T + bo + x0   (M = B*S = 8192, K = F, fp32 out)
    mma_gemm<2, false><<<dim3(4, 64, 1), 256, SMEM_SZ>>>(
        finH, WoH, out,
        F_, F_, F_, D_,
        0, 0, 0, 0, 0, 0,
        x0, D_, 0, 0,
        bo, 0, 1.0f,
        nullptr, 0);
}

// round 7
// speedup vs baseline: 3.5767x; 1.0172x over previous
#include <cuda_runtime.h>
#include <cuda_fp16.h>
#include <cstdint>

#define H_ 3
#define L_ 2
#define B_ 16
#define S_ 512
#define D_ 512
#define F_ (H_ * L_ * D_)   // 3072

// Scratch (no cudaMalloc allowed) — fp16 operand buffers
__device__ __align__(16) __half g_adjH[(size_t)H_ * B_ * S_ * S_];  // 25 MB
__device__ __align__(16) __half g_AxH[(size_t)H_ * B_ * S_ * D_];   // 25 MB
__device__ __align__(16) __half g_finH[(size_t)B_ * S_ * F_];       // 50 MB
__device__ __align__(16) __half g_XTH[(size_t)H_ * B_ * D_ * S_];   // 25 MB
__device__ __align__(16) __half g_X0TH[(size_t)B_ * D_ * S_];       // 8 MB
__device__ __align__(16) __half g_WgH[(size_t)H_ * L_ * D_ * D_];   // 3 MB
__device__ __align__(16) __half g_WoH[(size_t)D_ * F_];             // 3 MB
__device__ float g_denom[H_ * B_ * S_];                             // 96 KB

// ---------------------------------------------------------------------------
__device__ __forceinline__ uint32_t smem_u32(const void* p) {
    uint32_t a;
    asm("{ .reg .u64 t; cvta.to.shared.u64 t, %1; cvt.u32.u64 %0, t; }" : "=r"(a) : "l"(p));
    return a;
}
#define CP_ASYNC16(dst, src) \
    asm volatile("cp.async.cg.shared.global [%0], [%1], 16;" :: "r"(dst), "l"(src))
#define CP_COMMIT() asm volatile("cp.async.commit_group;")
#define CP_WAIT(n)  asm volatile("cp.async.wait_group %0;" :: "n"(n))

#define LDSM4(r0, r1, r2, r3, addr) \
    asm volatile("ldmatrix.sync.aligned.m8n8.x4.shared.b16 {%0,%1,%2,%3}, [%4];" \
        : "=r"(r0), "=r"(r1), "=r"(r2), "=r"(r3) : "r"(addr))

#define MMA_F16(c, a, b0, b1) \
    asm volatile("mma.sync.aligned.m16n8k16.row.col.f32.f16.f16.f32 " \
        "{%0,%1,%2,%3}, {%4,%5,%6,%7}, {%8,%9}, {%0,%1,%2,%3};" \
        : "+f"((c)[0]), "+f"((c)[1]), "+f"((c)[2]), "+f"((c)[3]) \
        : "r"((a)[0]), "r"((a)[1]), "r"((a)[2]), "r"((a)[3]), \
          "r"(b0), "r"(b1))

__device__ __forceinline__ __half toh(float x)  { return __float2half_rn(x); }
__device__ __forceinline__ __half toh(__half x) { return x; }

// ---------------------------------------------------------------------------
// Per row (h,b,s): den = 1 + sum_t adj (exact fp32), adjH = half(adj)
// ---------------------------------------------------------------------------
__global__ void denom_round_kernel(const float* __restrict__ adj,
                                   float* __restrict__ den,
                                   __half* __restrict__ adjH)
{
    int gw = (blockIdx.x * blockDim.x + threadIdx.x) >> 5;
    int lane = threadIdx.x & 31;
    if (gw >= H_ * B_ * S_) return;
    const float4* p = (const float4*)(adj + (long)gw * S_);
    __half2* q = (__half2*)(adjH + (long)gw * S_);
    float s = 0.f;
    #pragma unroll 2
    for (int i = lane; i < S_ / 4; i += 32) {
        float4 v = p[i];
        s += v.x + v.y + v.z + v.w;
        q[2 * i]     = __floats2half2_rn(v.x, v.y);
        q[2 * i + 1] = __floats2half2_rn(v.z, v.w);
    }
    #pragma unroll
    for (int o = 16; o > 0; o >>= 1) s += __shfl_xor_sync(0xffffffffu, s, o);
    if (lane == 0) den[gw] = s + 1.0f;
}

__global__ void roundcopy_half(const float* __restrict__ src,
                               __half* __restrict__ dst, int n4)
{
    int i = blockIdx.x * blockDim.x + threadIdx.x;
    if (i >= n4) return;
    float4 v = ((const float4*)src)[i];
    ((__half2*)dst)[2 * i]     = __floats2half2_rn(v.x, v.y);
    ((__half2*)dst)[2 * i + 1] = __floats2half2_rn(v.z, v.w);
}

// ---------------------------------------------------------------------------
// XT[h][b][d][s] = half( X[...][s][d] )
// ---------------------------------------------------------------------------
template <typename T>
__global__ void transpose_kernel(const T* __restrict__ X, int ldx,
                                 long xHead, long xBatch,
                                 __half* __restrict__ XT, long tHead)
{
    __shared__ __half t[32][33];
    int z = blockIdx.z;
    int hz = z >> 4, bz = z & 15;
    int s0 = blockIdx.x * 32, d0 = blockIdx.y * 32;
    const T* Xb = X + (long)hz * xHead + (long)bz * xBatch;
    __half* Tb = XT + (long)hz * tHead + (long)bz * D_ * S_;
    int tx = threadIdx.x, ty = threadIdx.y;  // 32 x 8
    #pragma unroll
    for (int i = 0; i < 32; i += 8)
        t[ty + i][tx] = toh(Xb[(long)(s0 + ty + i) * ldx + d0 + tx]);
    __syncthreads();
    #pragma unroll
    for (int i = 0; i < 32; i += 8)
        Tb[(long)(d0 + ty + i) * S_ + s0 + tx] = t[tx][ty + i];
}

// ---------------------------------------------------------------------------
// FP16 mma.sync GEMM (fp32 accum): C[M,N] = A[M,K] * B[N,K]^T, K-major halves.
// 3-stage cp.async pipeline, ONE barrier per k-tile, B-fragment double buffer.
// z encodes (head = z>>4, batch = z&15).
// MODE 0: Chalf = acc + epi[m][n]             (epi fp32 or fp16 per EPI_HALF)
// MODE 1: Chalf = relu((acc + biasScale*bias[n]) / denom[z,m])
// MODE 2: Cfloat = acc + bias[n] + epi[m][n]  (epi fp32)
// ---------------------------------------------------------------------------
constexpr int BM = 128, BN = 128, BK = 64;        // BK in halves (128 bytes)
constexpr int LDSROW = 72;                        // halves; 144B stride -> conflict-free
constexpr int STAGE_HALVES = 2 * BM * LDSROW;     // A + B = 18432
constexpr int STAGE_BYTES = STAGE_HALVES * 2;     // 36864
constexpr int NSTAGE = 3;
constexpr int SMEM_SZ = NSTAGE * STAGE_BYTES;     // 110592

template <int MODE, bool EPI_HALF>
__global__ __launch_bounds__(256, 2)
void mma_gemm(const __half* __restrict__ A, const __half* __restrict__ Bm,
              void* __restrict__ C,
              int K, int lda, int ldb, int ldc,
              long aHead, long aBatch, long bHead, long bBatch,
              long cHead, long cBatch,
              const void* __restrict__ epi, int epiLd, long epiHead, long epiBatch,
              const float* __restrict__ bias, long biasHead, float biasScale,
              const float* __restrict__ denom, int denomStride)
{
    extern __shared__ char smemc[];
    const int tid = threadIdx.x;
    const int wid = tid >> 5, lane = tid & 31;
    const int bx = blockIdx.x, by = blockIdx.y, z = blockIdx.z;
    const int hz = z >> 4, bz = z & 15;

    const uint32_t sbase = smem_u32(smemc);

    const __half* Ab = A + (long)hz * aHead + (long)bz * aBatch + (long)(by * BM) * lda;
    const __half* Bb = Bm + (long)hz * bHead + (long)bz * bBatch + (long)(bx * BN) * ldb;

    // cp.async: 2 threads per 128B row, 4 x 16B chunks each
    const int ldrow = tid >> 1;
    const int ldh0  = (tid & 1) * 32;      // half offset within row

    auto load_stage = [&](int s, int kt) {
        const long k0 = (long)kt * BK + ldh0;
        const __half* ag = Ab + (long)ldrow * lda + k0;
        const __half* bg = Bb + (long)ldrow * ldb + k0;
        uint32_t da = sbase + (uint32_t)(s * STAGE_BYTES)
                    + (uint32_t)(ldrow * LDSROW + ldh0) * 2u;
        uint32_t db = da + (uint32_t)(BM * LDSROW) * 2u;
        #pragma unroll
        for (int i = 0; i < 4; ++i) {
            CP_ASYNC16(da + i * 16u, ag + i * 8);
            CP_ASYNC16(db + i * 16u, bg + i * 8);
        }
    };

    // warp tiling: 2 (m) x 4 (n); each warp 64x32
    const int m0 = (wid & 1) * 64;
    const int n0 = (wid >> 1) * 32;
    const int lq = lane >> 2;
    const int lr = lane & 3;

    // ldmatrix base addresses (stage 0, ks = 0)
    const uint32_t aAddr0 = sbase
        + (uint32_t)((m0 + ((lane >> 3) & 1) * 8 + (lane & 7)) * LDSROW) * 2u
        + (uint32_t)(lane >> 4) * 16u;
    const uint32_t bAddr0 = sbase + (uint32_t)(BM * LDSROW) * 2u
        + (uint32_t)((n0 + (lane >> 4) * 8 + (lane & 7)) * LDSROW) * 2u
        + (uint32_t)((lane >> 3) & 1) * 16u;

    float c[4][4][4];
    #pragma unroll
    for (int mi = 0; mi < 4; ++mi)
        #pragma unroll
        for (int ni = 0; ni < 4; ++ni)
            #pragma unroll
            for (int j = 0; j < 4; ++j) c[mi][ni][j] = 0.f;

    const int numK = K >> 6;   // >= 8 for all our GEMMs

    load_stage(0, 0); CP_COMMIT();
    load_stage(1, 1); CP_COMMIT();

    for (int kt = 0; kt < numK; ++kt) {
        if (kt + 1 < numK) { CP_WAIT(1); } else { CP_WAIT(0); }
        __syncthreads();   // single barrier per k-tile (3-stage WAR covered)
        if (kt + 2 < numK) {
            load_stage((kt + 2) % NSTAGE, kt + 2);
            CP_COMMIT();
        }

        const uint32_t sOff = (uint32_t)(kt % NSTAGE) * STAGE_BYTES;
        uint32_t a[4][4], b[2][2][4];

        // preload B fragments for ks = 0
        #pragma unroll
        for (int p = 0; p < 2; ++p)
            LDSM4(b[0][p][0], b[0][p][1], b[0][p][2], b[0][p][3],
                  bAddr0 + sOff + (uint32_t)p * (16u * LDSROW * 2u));

        #pragma unroll
        for (int ks = 0; ks < 4; ++ks) {          // k16 steps within BK=64
            const uint32_t kOff = sOff + (uint32_t)ks * 32u;   // 16 halves
            const int cur = ks & 1;
            // prefetch next B fragments under this step's MMAs
            if (ks < 3) {
                const uint32_t kOffN = sOff + (uint32_t)(ks + 1) * 32u;
                #pragma unroll
                for (int p = 0; p < 2; ++p)
                    LDSM4(b[cur ^ 1][p][0], b[cur ^ 1][p][1],
                          b[cur ^ 1][p][2], b[cur ^ 1][p][3],
                          bAddr0 + kOffN + (uint32_t)p * (16u * LDSROW * 2u));
            }
            #pragma unroll
            for (int mi = 0; mi < 4; ++mi)
                LDSM4(a[mi][0], a[mi][1], a[mi][2], a[mi][3],
                      aAddr0 + kOff + (uint32_t)mi * (16u * LDSROW * 2u));
            #pragma unroll
            for (int mi = 0; mi < 4; ++mi)
                #pragma unroll
                for (int ni = 0; ni < 4; ++ni)
                    MMA_F16(c[mi][ni], a[mi], b[cur][ni >> 1][(ni & 1) * 2],
                            b[cur][ni >> 1][(ni & 1) * 2 + 1]);
        }
    }

    // ---------------- epilogue ----------------
    const float* biasP = (MODE == 1 || MODE == 2) ? (bias + (long)hz * biasHead) : nullptr;

    #pragma unroll
    for (int mi = 0; mi < 4; ++mi) {
        const int r0 = by * BM + m0 + mi * 16 + lq;
        float invd0 = 1.f, invd1 = 1.f;
        if (MODE == 1) {
            invd0 = 1.0f / denom[(long)z * denomStride + r0];
            invd1 = 1.0f / denom[(long)z * denomStride + r0 + 8];
        }
        #pragma unroll
        for (int ni = 0; ni < 4; ++ni) {
            const int col = bx * BN + n0 + ni * 8 + 2 * lr;
            float v00 = c[mi][ni][0], v01 = c[mi][ni][1];
            float v10 = c[mi][ni][2], v11 = c[mi][ni][3];
            if (MODE == 0) {
                if (EPI_HALF) {
                    const __half* Eb = (const __half*)epi
                        + (long)hz * epiHead + (long)bz * epiBatch;
                    float2 e0 = __half22float2(*(const __half2*)(Eb + (long)r0 * epiLd + col));
                    float2 e1 = __half22float2(*(const __half2*)(Eb + (long)(r0 + 8) * epiLd + col));
                    v00 += e0.x; v01 += e0.y; v10 += e1.x; v11 += e1.y;
                } else {
                    const float* Eb = (const float*)epi
                        + (long)hz * epiHead + (long)bz * epiBatch;
                    float2 e0 = *(const float2*)(Eb + (long)r0 * epiLd + col);
                    float2 e1 = *(const float2*)(Eb + (long)(r0 + 8) * epiLd + col);
                    v00 += e0.x; v01 += e0.y; v10 += e1.x; v11 += e1.y;
                }
                __half* Cb = (__half*)C + (long)hz * cHead + (long)bz * cBatch;
                *(__half2*)(Cb + (long)r0 * ldc + col)       = __floats2half2_rn(v00, v01);
                *(__half2*)(Cb + (long)(r0 + 8) * ldc + col) = __floats2half2_rn(v10, v11);
            } else if (MODE == 1) {
                const float b0 = biasScale * biasP[col];
                const float b1 = biasScale * biasP[col + 1];
                v00 = fmaxf((v00 + b0) * invd0, 0.f);
                v01 = fmaxf((v01 + b1) * invd0, 0.f);
                v10 = fmaxf((v10 + b0) * invd1, 0.f);
                v11 = fmaxf((v11 + b1) * invd1, 0.f);
                __half* Cb = (__half*)C + (long)hz * cHead + (long)bz * cBatch;
                *(__half2*)(Cb + (long)r0 * ldc + col)       = __floats2half2_rn(v00, v01);
                *(__half2*)(Cb + (long)(r0 + 8) * ldc + col) = __floats2half2_rn(v10, v11);
            } else {  // MODE 2: fp32 output, fp32 epi (residual) + bias
                const float* Eb = (const float*)epi;
                float2 e0 = *(const float2*)(Eb + (long)r0 * epiLd + col);
                float2 e1 = *(const float2*)(Eb + (long)(r0 + 8) * epiLd + col);
                const float b0 = biasP[col], b1 = biasP[col + 1];
                v00 += e0.x + b0; v01 += e0.y + b1;
                v10 += e1.x + b0; v11 += e1.y + b1;
                float* Cb = (float*)C;
                float2 w0 = {v00, v01}, w1 = {v10, v11};
                *(float2*)(Cb + (long)r0 * ldc + col) = w0;
                *(float2*)(Cb + (long)(r0 + 8) * ldc + col) = w1;
            }
        }
    }
}

// ---------------------------------------------------------------------------
extern "C" void kernel_launch(void* const* d_in, const int* in_sizes, int n_in,
                              void* d_out, int out_size)
{
    const float* adj = (const float*)d_in[0];   // [H,B,S,S]
    const float* x0  = (const float*)d_in[1];   // [B,S,D]
    const float* Wg  = (const float*)d_in[4];   // [H*L, D, D]
    const float* bg  = (const float*)d_in[5];   // [H*L, D]
    const float* Wo  = (const float*)d_in[6];   // [D, F]
    const float* bo  = (const float*)d_in[7];   // [D]
    float* out = (float*)d_out;                 // [B,S,D]

    __half *adjH, *AxH, *finH, *XTH, *X0TH, *WgH, *WoH;
    float* den;
    cudaGetSymbolAddress((void**)&adjH, g_adjH);
    cudaGetSymbolAddress((void**)&AxH,  g_AxH);
    cudaGetSymbolAddress((void**)&finH, g_finH);
    cudaGetSymbolAddress((void**)&XTH,  g_XTH);
    cudaGetSymbolAddress((void**)&X0TH, g_X0TH);
    cudaGetSymbolAddress((void**)&WgH,  g_WgH);
    cudaGetSymbolAddress((void**)&WoH,  g_WoH);
    cudaGetSymbolAddress((void**)&den,  g_denom);

    cudaFuncSetAttribute(mma_gemm<0, false>, cudaFuncAttributeMaxDynamicSharedMemorySize, SMEM_SZ);
    cudaFuncSetAttribute(mma_gemm<0, true>,  cudaFuncAttributeMaxDynamicSharedMemorySize, SMEM_SZ);
    cudaFuncSetAttribute(mma_gemm<1, false>, cudaFuncAttributeMaxDynamicSharedMemorySize, SMEM_SZ);
    cudaFuncSetAttribute(mma_gemm<2, false>, cudaFuncAttributeMaxDynamicSharedMemorySize, SMEM_SZ);

    // ---- prep: denom + fp16 operand copies ----
    denom_round_kernel<<<(H_ * B_ * S_) / 8, 256>>>(adj, den, adjH);
    roundcopy_half<<<(H_ * L_ * D_ * D_ / 4 + 255) / 256, 256>>>(Wg, WgH, H_ * L_ * D_ * D_ / 4);
    roundcopy_half<<<(D_ * F_ / 4 + 255) / 256, 256>>>(Wo, WoH, D_ * F_ / 4);
    transpose_kernel<float><<<dim3(16, 16, B_), dim3(32, 8)>>>(
        x0, D_, 0, (long)S_ * D_, X0TH, 0);

    const long SS = (long)S_ * S_, SD = (long)S_ * D_, SF = (long)S_ * F_;
    const long DS = (long)D_ * S_, DD = (long)D_ * D_;

    for (int l = 0; l < L_; ++l) {
        // GEMM1 (all heads): AxH[h] = adj[h] @ X + X
        if (l == 0) {
            mma_gemm<0, false><<<dim3(4, 4, H_ * B_), 256, SMEM_SZ>>>(
                adjH, X0TH, AxH,
                S_, S_, S_, D_,
                (long)B_ * SS, SS, 0, DS, (long)B_ * SD, SD,
                x0, D_, 0, SD,
                nullptr, 0, 0.f,
                nullptr, 0);
        } else {
            mma_gemm<0, true><<<dim3(4, 4, H_ * B_), 256, SMEM_SZ>>>(
                adjH, XTH, AxH,
                S_, S_, S_, D_,
                (long)B_ * SS, SS, (long)B_ * DS, DS, (long)B_ * SD, SD,
                finH, F_, (long)L_ * D_, SF,   // epi = prev layer output (fp16)
                nullptr, 0, 0.f,
                nullptr, 0);
        }

        // GEMM2 (all heads): finH[.., (h*L+l)*D ..] = relu((AxH @ Wg^T + 2b)/den)
        mma_gemm<1, false><<<dim3(4, 4, H_ * B_), 256, SMEM_SZ>>>(
            AxH, WgH + (long)l * DD, finH + (long)l * D_,
            D_, D_, D_, F_,
            (long)B_ * SD, SD, (long)L_ * DD, 0, (long)L_ * D_, SF,
            nullptr, 0, 0, 0,
            bg + (long)l * D_, (long)L_ * D_, 2.0f,
            den, S_);

        // layer-0 outputs -> transposed fp16 for layer-1 GEMM1 B operand
        if (l == 0)
            transpose_kernel<__half><<<dim3(16, 16, H_ * B_), dim3(32, 8)>>>(
                finH, F_, (long)L_ * D_, SF, XTH, (long)B_ * DS);
    }

    // Final: out = finH @ Wo^T + bo + x0   (M = B*S = 8192, K = F, fp32 out)
    mma_gemm<2, false><<<dim3(4, 64, 1), 256, SMEM_SZ>>>(
        finH, WoH, out,
        F_, F_, F_, D_,
        0, 0, 0, 0, 0, 0,
        x0, D_, 0, 0,
        bo, 0, 1.0f,
        nullptr, 0);
}